// round 1
// baseline (speedup 1.0000x reference)
#include <cuda_runtime.h>

#define SEQ 2048
#define NB 4
#define NH 16
#define HD 64
#define HID 1024
#define MTOT (NB*SEQ)
#define GK 1024
#define NEG -1e30f
#define ATT_SCALE 0.125f

// Scratch (device globals: allocation-free rule)
__device__ float g_q[NB*NH*SEQ*HD];
__device__ float g_k[NB*NH*SEQ*HD];
__device__ float g_v[NB*NH*SEQ*HD];
__device__ float g_att[NB*NH*SEQ*HD];

__device__ __forceinline__ unsigned f2tf(float f){
    unsigned u; asm("cvt.rna.tf32.f32 %0, %1;" : "=r"(u) : "f"(f)); return u;
}

__device__ __forceinline__ void mma8(float* c, const unsigned* a, unsigned b0, unsigned b1){
    asm volatile(
      "mma.sync.aligned.m16n8k8.row.col.f32.tf32.tf32.f32 "
      "{%0,%1,%2,%3},{%4,%5,%6,%7},{%8,%9},{%0,%1,%2,%3};\n"
      : "+f"(c[0]), "+f"(c[1]), "+f"(c[2]), "+f"(c[3])
      : "r"(a[0]), "r"(a[1]), "r"(a[2]), "r"(a[3]), "r"(b0), "r"(b1));
}

__device__ __forceinline__ void cp16(float* sptr, const float* g){
    unsigned s = (unsigned)__cvta_generic_to_shared(sptr);
    asm volatile("cp.async.cg.shared.global [%0], [%1], 16;\n" :: "r"(s), "l"(g));
}

// ---------------------------------------------------------------------------
// Generic tf32 GEMM: Y[M,N] = A[M,K] @ W[N,K]^T + bias
// a_mode : 0 = A row-major [M,K] (= x)      1 = gather from g_att [B,H,S,D]
// out_sel: 0 = Yout [M,N]  1/2/3 = scatter into g_q/g_k/g_v as [B,H,S,D]
// Tiles: BM=128, BN=128, BK=32. 256 threads = 8 warps (4m x 2n), warp 32x64.
// ---------------------------------------------------------------------------
__global__ void __launch_bounds__(256)
gemm_tf32(const float* __restrict__ A, const float* __restrict__ W,
          const float* __restrict__ bias, float* Yout, int a_mode, int out_sel)
{
    extern __shared__ float sm[];   // 2 stages x (128*36 A + 128*36 B) floats
    const int tid = threadIdx.x, lane = tid & 31, warp = tid >> 5;
    const int wm = warp & 3, wn = warp >> 2;
    const int n0 = blockIdx.x * 128, m0 = blockIdx.y * 128;

    const float* Ap = a_mode ? (const float*)g_att : A;
    float* Yt = (out_sel == 0) ? Yout : (out_sel == 1 ? g_q : (out_sel == 2 ? g_k : g_v));

    float c[2][8][4];
    #pragma unroll
    for (int i = 0; i < 2; i++)
      #pragma unroll
      for (int j = 0; j < 8; j++)
        #pragma unroll
        for (int v = 0; v < 4; v++) c[i][j][v] = 0.f;

    auto load_stage = [&](int buf, int kt){
        float* As = sm + buf * 9216;
        float* Bs = As + 4608;
        const int k0 = kt * 32;
        #pragma unroll
        for (int i = 0; i < 4; i++){
            int slot = tid + i * 256;          // 1024 float4 slots
            int row = slot >> 3, c4 = slot & 7;
            const float* src;
            if (!a_mode){
                src = Ap + (size_t)(m0 + row) * GK + k0 + c4 * 4;
            } else {
                int m = m0 + row, kg = k0 + c4 * 4;
                src = Ap + ((size_t)(((m >> 11) * NH + (kg >> 6)) * SEQ + (m & 2047)) * HD + (kg & 63));
            }
            cp16(As + row * 36 + c4 * 4, src);
        }
        #pragma unroll
        for (int i = 0; i < 4; i++){
            int slot = tid + i * 256;
            int row = slot >> 3, c4 = slot & 7;
            cp16(Bs + row * 36 + c4 * 4, W + (size_t)(n0 + row) * GK + k0 + c4 * 4);
        }
        asm volatile("cp.async.commit_group;\n");
    };

    load_stage(0, 0);
    const int NK = GK / 32;   // 32
    for (int kt = 0; kt < NK; kt++){
        if (kt + 1 < NK){
            load_stage((kt + 1) & 1, kt + 1);
            asm volatile("cp.async.wait_group 1;\n");
        } else {
            asm volatile("cp.async.wait_group 0;\n");
        }
        __syncthreads();
        const float* As = sm + (kt & 1) * 9216;
        const float* Bs = As + 4608;
        #pragma unroll
        for (int ks = 0; ks < 4; ks++){
            unsigned a[2][4];
            const int kk = ks * 8 + (lane & 3);
            const int r  = wm * 32 + (lane >> 2);
            a[0][0] = f2tf(As[ r      * 36 + kk    ]);
            a[0][1] = f2tf(As[(r + 8) * 36 + kk    ]);
            a[0][2] = f2tf(As[ r      * 36 + kk + 4]);
            a[0][3] = f2tf(As[(r + 8) * 36 + kk + 4]);
            a[1][0] = f2tf(As[(r + 16) * 36 + kk    ]);
            a[1][1] = f2tf(As[(r + 24) * 36 + kk    ]);
            a[1][2] = f2tf(As[(r + 16) * 36 + kk + 4]);
            a[1][3] = f2tf(As[(r + 24) * 36 + kk + 4]);
            #pragma unroll
            for (int nt = 0; nt < 8; nt++){
                const int n = wn * 64 + nt * 8 + (lane >> 2);
                unsigned b0 = f2tf(Bs[n * 36 + kk]);
                unsigned b1 = f2tf(Bs[n * 36 + kk + 4]);
                mma8(c[0][nt], a[0], b0, b1);
                mma8(c[1][nt], a[1], b0, b1);
            }
        }
        __syncthreads();
    }

    #pragma unroll
    for (int mt = 0; mt < 2; mt++)
      #pragma unroll
      for (int nt = 0; nt < 8; nt++){
          const int rr = m0 + wm * 32 + mt * 16 + (lane >> 2);
          const int nn = n0 + wn * 64 + nt * 8 + 2 * (lane & 3);
          #pragma unroll
          for (int v = 0; v < 4; v++){
              const int m = rr + ((v >= 2) ? 8 : 0);
              const int n = nn + (v & 1);
              const float val = c[mt][nt][v] + bias[n];
              if (out_sel == 0)
                  Yt[(size_t)m * HID + n] = val;
              else
                  Yt[((size_t)((m >> 11) * NH + (n >> 6)) * SEQ + (m & 2047)) * HD + (n & 63)] = val;
          }
      }
}

// ---------------------------------------------------------------------------
// Band attention: one block per (tile of 64 rows, head, batch).
// Columns = 4 global cols (t>0) + sliding band [i0-32, i0+95] (<=132 total,
// padded to 144 for 18 n-tiles of 8). Rows i<4 skipped (global-row kernel).
// ---------------------------------------------------------------------------
__global__ void __launch_bounds__(256)
attn_band()
{
    extern __shared__ float sm[];
    float* Qs   = sm;                 // 64  x 68
    float* Ks   = Qs + 64 * 68;       // 144 x 68
    float* Ss   = Ks + 144 * 68;      // 64  x 148
    float* Vs   = Ss + 64 * 148;      // 144 x 72
    float* rinv = Vs + 144 * 72;      // 64

    const int tid = threadIdx.x, lane = tid & 31, warp = tid >> 5;
    const int t = blockIdx.x, h = blockIdx.y, b = blockIdx.z;
    const int i0 = t * 64;
    const int nglob = (t == 0) ? 0 : 4;
    const int jlo   = (t == 0) ? 0 : (i0 - 32);
    const int jhi   = min(SEQ - 1, i0 + 95);
    const int NC    = nglob + (jhi - jlo + 1);
    const size_t base = ((size_t)(b * NH + h)) * SEQ * HD;

    // ---- load Q tile ----
    #pragma unroll
    for (int i = 0; i < 4; i++){
        int slot = tid + i * 256;                 // 1024 slots
        int row = slot >> 4, d4 = slot & 15;
        *(float4*)(Qs + row * 68 + d4 * 4) =
            *(const float4*)(g_q + base + (size_t)(i0 + row) * HD + d4 * 4);
    }
    // ---- load K/V columns (zero pad rows NC..143) ----
    #pragma unroll
    for (int i = 0; i < 9; i++){
        int slot = tid + i * 256;                 // 2304 slots
        int cc = slot >> 4, d4 = slot & 15;
        float4 kv = make_float4(0.f,0.f,0.f,0.f);
        float4 vv = kv;
        if (cc < NC){
            int j = (cc < nglob) ? cc : jlo + (cc - nglob);
            kv = *(const float4*)(g_k + base + (size_t)j * HD + d4 * 4);
            vv = *(const float4*)(g_v + base + (size_t)j * HD + d4 * 4);
        }
        *(float4*)(Ks + cc * 68 + d4 * 4) = kv;
        *(float4*)(Vs + cc * 72 + d4 * 4) = vv;
    }
    __syncthreads();

    // ---- scores: S = (Q K^T) * scale, masked.  warp = (mt, nt-half of 9) ----
    {
        const int mt = warp >> 1, ntb = (warp & 1) * 9;
        float cs[9][4];
        #pragma unroll
        for (int q = 0; q < 9; q++)
            #pragma unroll
            for (int v = 0; v < 4; v++) cs[q][v] = 0.f;
        #pragma unroll
        for (int ks = 0; ks < 8; ks++){
            const int kk = ks * 8 + (lane & 3);
            const int r  = mt * 16 + (lane >> 2);
            unsigned a[4];
            a[0] = f2tf(Qs[ r      * 68 + kk    ]);
            a[1] = f2tf(Qs[(r + 8) * 68 + kk    ]);
            a[2] = f2tf(Qs[ r      * 68 + kk + 4]);
            a[3] = f2tf(Qs[(r + 8) * 68 + kk + 4]);
            #pragma unroll
            for (int q = 0; q < 9; q++){
                const int n = (ntb + q) * 8 + (lane >> 2);
                unsigned b0 = f2tf(Ks[n * 68 + kk]);
                unsigned b1 = f2tf(Ks[n * 68 + kk + 4]);
                mma8(cs[q], a, b0, b1);
            }
        }
        #pragma unroll
        for (int q = 0; q < 9; q++){
            const int r0 = mt * 16 + (lane >> 2);
            const int c0 = (ntb + q) * 8 + 2 * (lane & 3);
            #pragma unroll
            for (int v = 0; v < 4; v++){
                const int r  = r0 + ((v >= 2) ? 8 : 0);
                const int cc = c0 + (v & 1);
                float sv = NEG;
                if (cc < NC){
                    int j = (cc < nglob) ? cc : jlo + (cc - nglob);
                    int i = i0 + r;
                    int dlt = i - j; if (dlt < 0) dlt = -dlt;
                    if (j < 4 || dlt <= 32) sv = cs[q][v] * ATT_SCALE;
                }
                Ss[r * 148 + cc] = sv;
            }
        }
    }
    __syncthreads();

    // ---- softmax (4 threads per row, 36 cols each) ----
    {
        const int r = tid >> 2, p4 = tid & 3;
        float* row = Ss + r * 148 + p4 * 36;
        float mx = NEG;
        #pragma unroll
        for (int cc = 0; cc < 36; cc++) mx = fmaxf(mx, row[cc]);
        mx = fmaxf(mx, __shfl_xor_sync(0xffffffffu, mx, 1));
        mx = fmaxf(mx, __shfl_xor_sync(0xffffffffu, mx, 2));
        float ssum = 0.f;
        #pragma unroll
        for (int cc = 0; cc < 36; cc++){
            float p = __expf(row[cc] - mx);
            row[cc] = p; ssum += p;
        }
        ssum += __shfl_xor_sync(0xffffffffu, ssum, 1);
        ssum += __shfl_xor_sync(0xffffffffu, ssum, 2);
        if (p4 == 0) rinv[r] = 1.f / ssum;
    }
    __syncthreads();

    // ---- PV: O = P V (K-dim 144, zero-padded).  warp = (mt, nt-quad) ----
    {
        const int mt = warp >> 1, ntb = (warp & 1) * 4;
        float co[4][4];
        #pragma unroll
        for (int q = 0; q < 4; q++)
            #pragma unroll
            for (int v = 0; v < 4; v++) co[q][v] = 0.f;
        #pragma unroll
        for (int ks = 0; ks < 18; ks++){
            const int kk = ks * 8 + (lane & 3);
            const int r  = mt * 16 + (lane >> 2);
            unsigned a[4];
            a[0] = f2tf(Ss[ r      * 148 + kk    ]);
            a[1] = f2tf(Ss[(r + 8) * 148 + kk    ]);
            a[2] = f2tf(Ss[ r      * 148 + kk + 4]);
            a[3] = f2tf(Ss[(r + 8) * 148 + kk + 4]);
            #pragma unroll
            for (int q = 0; q < 4; q++){
                const int d = (ntb + q) * 8 + (lane >> 2);
                unsigned b0 = f2tf(Vs[ kk      * 72 + d]);
                unsigned b1 = f2tf(Vs[(kk + 4) * 72 + d]);
                mma8(co[q], a, b0, b1);
            }
        }
        #pragma unroll
        for (int q = 0; q < 4; q++){
            const int r0 = mt * 16 + (lane >> 2);
            const int d0 = (ntb + q) * 8 + 2 * (lane & 3);
            #pragma unroll
            for (int v = 0; v < 4; v++){
                const int r = r0 + ((v >= 2) ? 8 : 0);
                const int d = d0 + (v & 1);
                const int i = i0 + r;
                if (i >= 4)
                    g_att[base + (size_t)i * HD + d] = co[q][v] * rinv[r];
            }
        }
    }
}

// ---------------------------------------------------------------------------
// Global rows (i < 4): dense attention over all 2048 cols, fp32.
// One block per (row, head, batch).
// ---------------------------------------------------------------------------
__global__ void __launch_bounds__(256)
attn_global()
{
    __shared__ float qs[HD];
    __shared__ float s[SEQ];
    __shared__ float red[256];
    const int tid = threadIdx.x;
    const int r = blockIdx.x, h = blockIdx.y, b = blockIdx.z;
    const size_t base = ((size_t)(b * NH + h)) * SEQ * HD;

    if (tid < HD) qs[tid] = g_q[base + (size_t)r * HD + tid];
    __syncthreads();

    for (int j = tid; j < SEQ; j += 256){
        const float4* kr = (const float4*)(g_k + base + (size_t)j * HD);
        const float4* qr = (const float4*)qs;
        float acc = 0.f;
        #pragma unroll
        for (int dd = 0; dd < 16; dd++){
            float4 kv = kr[dd], qv = qr[dd];
            acc += qv.x*kv.x + qv.y*kv.y + qv.z*kv.z + qv.w*kv.w;
        }
        s[j] = acc * ATT_SCALE;
    }
    __syncthreads();

    float lm = NEG;
    for (int j = tid; j < SEQ; j += 256) lm = fmaxf(lm, s[j]);
    red[tid] = lm; __syncthreads();
    for (int off = 128; off; off >>= 1){
        if (tid < off) red[tid] = fmaxf(red[tid], red[tid + off]);
        __syncthreads();
    }
    const float mx = red[0]; __syncthreads();

    float ls = 0.f;
    for (int j = tid; j < SEQ; j += 256){
        float p = __expf(s[j] - mx); s[j] = p; ls += p;
    }
    red[tid] = ls; __syncthreads();
    for (int off = 128; off; off >>= 1){
        if (tid < off) red[tid] += red[tid + off];
        __syncthreads();
    }
    const float ri = 1.f / red[0]; __syncthreads();

    const int d = tid & 63, ch = tid >> 6;
    float acc = 0.f;
    const float* vb = g_v + base + d;
    for (int j = ch * 512; j < ch * 512 + 512; j++) acc += s[j] * vb[(size_t)j * HD];
    red[tid] = acc; __syncthreads();
    if (tid < 64)
        g_att[base + (size_t)r * HD + tid] =
            (red[tid] + red[tid + 64] + red[tid + 128] + red[tid + 192]) * ri;
}

// ---------------------------------------------------------------------------
extern "C" void kernel_launch(void* const* d_in, const int* in_sizes, int n_in,
                              void* d_out, int out_size)
{
    const float* x  = (const float*)d_in[0];
    const float* Wq = (const float*)d_in[1];
    const float* bq = (const float*)d_in[2];
    const float* Wk = (const float*)d_in[3];
    const float* bk = (const float*)d_in[4];
    const float* Wv = (const float*)d_in[5];
    const float* bv = (const float*)d_in[6];
    const float* Wo = (const float*)d_in[7];
    const float* bo = (const float*)d_in[8];
    float* out = (float*)d_out;

    const int gsm  = 2 * 2 * 128 * 36 * 4;                                  // 73728 B
    const int asmb = (64*68 + 144*68 + 64*148 + 144*72 + 64) * 4;           // 136192 B
    cudaFuncSetAttribute(gemm_tf32, cudaFuncAttributeMaxDynamicSharedMemorySize, gsm);
    cudaFuncSetAttribute(attn_band, cudaFuncAttributeMaxDynamicSharedMemorySize, asmb);

    dim3 gg(HID / 128, MTOT / 128);
    gemm_tf32<<<gg, 256, gsm>>>(x, Wq, bq, nullptr, 0, 1);
    gemm_tf32<<<gg, 256, gsm>>>(x, Wk, bk, nullptr, 0, 2);
    gemm_tf32<<<gg, 256, gsm>>>(x, Wv, bv, nullptr, 0, 3);
    attn_band<<<dim3(SEQ / 64, NH, NB), 256, asmb>>>();
    attn_global<<<dim3(4, NH, NB), 256>>>();
    gemm_tf32<<<gg, 256, gsm>>>(x, Wo, bo, out, 1, 0);
}

// round 4
// speedup vs baseline: 2.0318x; 2.0318x over previous
#include <cuda_runtime.h>
#include <cuda_fp16.h>
#include <cstdint>

#define SEQ 2048
#define NB 4
#define NH 16
#define HD 64
#define HID 1024
#define MTOT (NB*SEQ)
#define NEG -1e30f
#define ATT_SCALE 0.125f

// ---------------- scratch (device globals; allocation-free rule) ----------
__device__ __half g_q[NB*NH*SEQ*HD];
__device__ __half g_k[NB*NH*SEQ*HD];
__device__ __half g_v[NB*NH*SEQ*HD];
__device__ __half g_att[NB*NH*SEQ*HD];
__device__ __half x_h[(size_t)MTOT*HID];
__device__ __half w_h[4*(size_t)HID*HID];

// ---------------- helpers -------------------------------------------------
__device__ __forceinline__ uint32_t smem_u32(const void* p){
    uint32_t a;
    asm("{ .reg .u64 t; cvta.to.shared.u64 t, %1; cvt.u32.u64 %0, t; }" : "=r"(a) : "l"(p));
    return a;
}
#define SWZ(b) ((b) ^ (((b) >> 3) & 0x70))

__device__ __forceinline__ void cp16s(uint32_t saddr, const void* g){
    asm volatile("cp.async.cg.shared.global [%0], [%1], 16;\n" :: "r"(saddr), "l"(g));
}
__device__ __forceinline__ void cp16z(uint32_t saddr, const void* g, int pred){
    int sz = pred ? 16 : 0;
    asm volatile("cp.async.cg.shared.global [%0], [%1], 16, %2;\n" :: "r"(saddr), "l"(g), "r"(sz));
}
__device__ __forceinline__ void ldm4(uint32_t* r, uint32_t addr){
    asm volatile("ldmatrix.sync.aligned.m8n8.x4.shared.b16 {%0,%1,%2,%3}, [%4];"
        : "=r"(r[0]),"=r"(r[1]),"=r"(r[2]),"=r"(r[3]) : "r"(addr));
}
__device__ __forceinline__ void ldm2(uint32_t* r, uint32_t addr){
    asm volatile("ldmatrix.sync.aligned.m8n8.x2.shared.b16 {%0,%1}, [%2];"
        : "=r"(r[0]),"=r"(r[1]) : "r"(addr));
}
__device__ __forceinline__ void ldm4t(uint32_t* r, uint32_t addr){
    asm volatile("ldmatrix.sync.aligned.m8n8.x4.trans.shared.b16 {%0,%1,%2,%3}, [%4];"
        : "=r"(r[0]),"=r"(r[1]),"=r"(r[2]),"=r"(r[3]) : "r"(addr));
}
__device__ __forceinline__ void mma16(float* c, const uint32_t* a, uint32_t b0, uint32_t b1){
    asm volatile(
      "mma.sync.aligned.m16n8k16.row.col.f32.f16.f16.f32 "
      "{%0,%1,%2,%3},{%4,%5,%6,%7},{%8,%9},{%0,%1,%2,%3};\n"
      : "+f"(c[0]), "+f"(c[1]), "+f"(c[2]), "+f"(c[3])
      : "r"(a[0]), "r"(a[1]), "r"(a[2]), "r"(a[3]), "r"(b0), "r"(b1));
}
// ldmatrix lane address for a 16x16 b16 tile at (row0, k0) in a swizzled
// 64-half (128B) row layout.  mats: [r0-7,k0-7],[r8-15,k0-7],[r0-7,k8-15],[r8-15,k8-15]
__device__ __forceinline__ uint32_t frag_addr(uint32_t tile, int row0, int k0, int lane){
    int r = row0 + (lane & 7) + ((lane >> 3) & 1) * 8;
    int c = k0 + ((lane >> 4) << 3);
    return tile + SWZ((uint32_t)(r * 128 + c * 2));
}

// ---------------------------------------------------------------------------
// fp32 -> fp16 conversion prepass.  sel<0 -> x_h, else w_h slab sel.
// Each thread: 8 elements.
// ---------------------------------------------------------------------------
__global__ void __launch_bounds__(256)
conv_h(const float* __restrict__ src, int sel, int n8)
{
    __half* dst = (sel < 0) ? x_h : (w_h + (size_t)sel * (HID*HID));
    int i = blockIdx.x * 256 + threadIdx.x;
    if (i < n8){
        float4 v0 = ((const float4*)src)[2*i];
        float4 v1 = ((const float4*)src)[2*i+1];
        __half2 h0 = __floats2half2_rn(v0.x, v0.y);
        __half2 h1 = __floats2half2_rn(v0.z, v0.w);
        __half2 h2 = __floats2half2_rn(v1.x, v1.y);
        __half2 h3 = __floats2half2_rn(v1.z, v1.w);
        uint2 o0, o1;
        o0.x = *(uint32_t*)&h0; o0.y = *(uint32_t*)&h1;
        o1.x = *(uint32_t*)&h2; o1.y = *(uint32_t*)&h3;
        ((uint2*)dst)[2*i]   = o0;
        ((uint2*)dst)[2*i+1] = o1;
    }
}

// ---------------------------------------------------------------------------
// fp16 GEMM:  Y[M,N] = A[M,K] @ W[N,K]^T + bias
// BM=128 BN=128 BK=64, 3-stage cp.async, SW128 smem, ldmatrix + mma.m16n8k16.
// qkv_mode=1: A = x_h, z = blockIdx.z selects W slab / bias / g_q|k|v scatter (half).
// qkv_mode=0: A = gather from g_att (half, [B,H,S,D]), W slab 3, fp32 out + bias.
// ---------------------------------------------------------------------------
#define GBK 64
#define A_BYT (128*128)         // 128 rows x 128B
#define STG   (2*A_BYT)         // A + B per stage
#define NSTG  3
#define NK    (HID/GBK)         // 16

__global__ void __launch_bounds__(256, 2)
gemm_h(const float* __restrict__ b0_, const float* __restrict__ b1_,
       const float* __restrict__ b2_, float* __restrict__ Yout, int qkv_mode)
{
    extern __shared__ char smem[];
    const uint32_t sb0 = smem_u32(smem);
    const int tid = threadIdx.x, lane = tid & 31, warp = tid >> 5;
    const int wm = warp & 3, wn = warp >> 2;            // 4m x 2n warps
    const int n0 = blockIdx.x * 128, m0 = blockIdx.y * 128;
    const int z  = qkv_mode ? blockIdx.z : 3;
    const __half* W    = w_h + (size_t)z * (HID*HID);
    const float* bias  = qkv_mode ? (z==0 ? b0_ : (z==1 ? b1_ : b2_)) : b0_;
    __half* dsth       = qkv_mode ? (z==0 ? g_q : (z==1 ? g_k : g_v)) : nullptr;

    float c[2][8][4];
    #pragma unroll
    for (int i = 0; i < 2; i++)
      #pragma unroll
      for (int j = 0; j < 8; j++)
        #pragma unroll
        for (int v = 0; v < 4; v++) c[i][j][v] = 0.f;

    auto load_chunk = [&](int ch, int slot){
        const int k0 = ch * GBK;
        const uint32_t uA = sb0 + slot * STG;
        const uint32_t uB = uA + A_BYT;
        #pragma unroll
        for (int i = 0; i < 4; i++){                    // A: 1024 16B ops
            int op = tid + i * 256;
            int row = op >> 3, at = op & 7;
            const __half* src;
            if (qkv_mode){
                src = x_h + (size_t)(m0 + row) * HID + k0 + at * 8;
            } else {
                int m = m0 + row, kg = k0 + at * 8;
                src = g_att + ((size_t)(((m >> 11) * NH + (kg >> 6)) * SEQ + (m & 2047)) * HD + (kg & 63));
            }
            cp16s(uA + SWZ((uint32_t)(row * 128 + at * 16)), src);
        }
        #pragma unroll
        for (int i = 0; i < 4; i++){                    // B: 1024 16B ops
            int op = tid + i * 256;
            int row = op >> 3, at = op & 7;
            cp16s(uB + SWZ((uint32_t)(row * 128 + at * 16)),
                  W + (size_t)(n0 + row) * HID + k0 + at * 8);
        }
        asm volatile("cp.async.commit_group;\n");
    };

    load_chunk(0, 0);
    load_chunk(1, 1);

    for (int ch = 0; ch < NK; ch++){
        if (ch + 2 < NK) load_chunk(ch + 2, (ch + 2) % NSTG);
        const int rem = NK - 1 - ch;
        if      (rem >= 2) asm volatile("cp.async.wait_group 2;\n");
        else if (rem == 1) asm volatile("cp.async.wait_group 1;\n");
        else               asm volatile("cp.async.wait_group 0;\n");
        __syncthreads();

        const uint32_t uA = sb0 + (ch % NSTG) * STG;
        const uint32_t uB = uA + A_BYT;
        #pragma unroll
        for (int ks = 0; ks < 4; ks++){
            uint32_t a[2][4];
            ldm4(a[0], frag_addr(uA, wm*32,      ks*16, lane));
            ldm4(a[1], frag_addr(uA, wm*32 + 16, ks*16, lane));
            uint32_t b[4][4];
            #pragma unroll
            for (int nb = 0; nb < 4; nb++)
                ldm4(b[nb], frag_addr(uB, wn*64 + nb*16, ks*16, lane));
            #pragma unroll
            for (int nt = 0; nt < 8; nt++){
                const int nb = nt >> 1, hi = nt & 1;
                mma16(c[0][nt], a[0], b[nb][hi], b[nb][2+hi]);
                mma16(c[1][nt], a[1], b[nb][hi], b[nb][2+hi]);
            }
        }
        __syncthreads();
    }

    // epilogue
    #pragma unroll
    for (int nt = 0; nt < 8; nt++){
        const int nn = n0 + wn*64 + nt*8 + 2*(lane & 3);
        float2 bv = *(const float2*)(bias + nn);
        #pragma unroll
        for (int mt = 0; mt < 2; mt++){
            const int rr = m0 + wm*32 + mt*16 + (lane >> 2);
            #pragma unroll
            for (int hf = 0; hf < 2; hf++){
                const int m = rr + hf*8;
                float v0 = c[mt][nt][hf*2]     + bv.x;
                float v1 = c[mt][nt][hf*2 + 1] + bv.y;
                if (qkv_mode){
                    __half2 hv = __floats2half2_rn(v0, v1);
                    __half* p = dsth + (((size_t)((m >> 11) * NH + (nn >> 6)) * SEQ + (m & 2047)) * HD + (nn & 63));
                    *(__half2*)p = hv;
                } else {
                    *(float2*)(Yout + (size_t)m * HID + nn) = make_float2(v0, v1);
                }
            }
        }
    }
}

// ---------------------------------------------------------------------------
// Band attention, fp16 mma: one block per (64-row tile, head, batch).
// Scores kept in fp32 registers; softmax via quad shuffles + small smem.
// smem: Qs 64x64h | Ks 144x64h | Vs 144x64h (all SW128) | Ps 64x168h | red
// ---------------------------------------------------------------------------
#define PS_STR 168
#define QS_OFF 0
#define KS_OFF 8192
#define VS_OFF 26624
#define PS_OFF 45056
#define RED_OFF 66560
#define ATT_SMEM (RED_OFF + 1024)

__global__ void __launch_bounds__(256, 3)
attn_band()
{
    extern __shared__ char smem[];
    const uint32_t sb = smem_u32(smem);
    const uint32_t uQ = sb + QS_OFF, uK = sb + KS_OFF, uV = sb + VS_OFF;
    __half* Ps  = (__half*)(smem + PS_OFF);
    float* mred = (float*)(smem + RED_OFF);      // [2][64]
    float* sred = mred + 128;                    // [2][64]

    const int tid = threadIdx.x, lane = tid & 31, warp = tid >> 5;
    const int q = lane & 3;
    const int t = blockIdx.x, h = blockIdx.y, b = blockIdx.z;
    const int i0 = t * 64;
    const int nglob = (t == 0) ? 0 : 4;
    const int jlo   = (t == 0) ? 0 : (i0 - 32);
    const int jhi   = min(SEQ - 1, i0 + 95);
    const int NC    = nglob + (jhi - jlo + 1);
    const size_t base = ((size_t)(b * NH + h)) * SEQ * HD;

    // ---- load Q (64 rows) ----
    #pragma unroll
    for (int i = 0; i < 2; i++){
        int op = tid + i * 256;                 // 512 ops
        int row = op >> 3, at = op & 7;
        cp16s(uQ + SWZ((uint32_t)(row * 128 + at * 16)),
              g_q + base + (size_t)(i0 + row) * HD + at * 8);
    }
    // ---- load K/V (144 rows each, zero-fill beyond NC) ----
    #pragma unroll
    for (int i = 0; i < 9; i++){
        int op = tid + i * 256;                 // 2304 ops
        int cc = op >> 4, at8 = op & 15;        // at8: 0-7 K, 8-15 V
        int at = at8 & 7;
        int isK = (at8 < 8);
        int valid = (cc < NC);
        int j = valid ? ((cc < nglob) ? cc : jlo + (cc - nglob)) : 0;
        const __half* src = (isK ? g_k : g_v) + base + (size_t)j * HD + at * 8;
        cp16z((isK ? uK : uV) + SWZ((uint32_t)(cc * 128 + at * 16)), src, valid);
    }
    asm volatile("cp.async.commit_group;\ncp.async.wait_group 0;\n");
    __syncthreads();

    // ---- scores: warps (wm rows 16 each, wn col-half 72 each) ----
    {
        const int wm = warp >> 1, wn = warp & 1;
        const int r_lo = wm*16 + (lane >> 2);
        float cs[9][4];
        #pragma unroll
        for (int nt = 0; nt < 9; nt++)
            #pragma unroll
            for (int v = 0; v < 4; v++) cs[nt][v] = 0.f;

        #pragma unroll
        for (int ks = 0; ks < 4; ks++){
            uint32_t qa[4];
            ldm4(qa, frag_addr(uQ, wm*16, ks*16, lane));
            uint32_t kb[4][4];
            #pragma unroll
            for (int nb = 0; nb < 4; nb++)
                ldm4(kb[nb], frag_addr(uK, wn*72 + nb*16, ks*16, lane));
            uint32_t k2[2];
            {
                int i2 = lane & 15;
                int rr = wn*72 + 64 + (i2 & 7);
                int cc = ks*16 + ((i2 >> 3) << 3);
                ldm2(k2, uK + SWZ((uint32_t)(rr * 128 + cc * 2)));
            }
            #pragma unroll
            for (int nt = 0; nt < 8; nt++){
                const int nb = nt >> 1, hi = nt & 1;
                mma16(cs[nt], qa, kb[nb][hi], kb[nb][2+hi]);
            }
            mma16(cs[8], qa, k2[0], k2[1]);
        }

        // mask + scale in regs
        #pragma unroll
        for (int nt = 0; nt < 9; nt++)
            #pragma unroll
            for (int v = 0; v < 4; v++){
                const int r  = r_lo + ((v >= 2) ? 8 : 0);
                const int cc = wn*72 + nt*8 + 2*q + (v & 1);
                float sv = NEG;
                if (cc < NC){
                    int j = (cc < nglob) ? cc : jlo + (cc - nglob);
                    int i = i0 + r;
                    int d = i - j; if (d < 0) d = -d;
                    if (j < 4 || d <= 32) sv = cs[nt][v] * ATT_SCALE;
                }
                cs[nt][v] = sv;
            }

        // row max (quad reduce)
        float mlo = NEG, mhi = NEG;
        #pragma unroll
        for (int nt = 0; nt < 9; nt++){
            mlo = fmaxf(mlo, fmaxf(cs[nt][0], cs[nt][1]));
            mhi = fmaxf(mhi, fmaxf(cs[nt][2], cs[nt][3]));
        }
        mlo = fmaxf(mlo, __shfl_xor_sync(0xffffffffu, mlo, 1));
        mlo = fmaxf(mlo, __shfl_xor_sync(0xffffffffu, mlo, 2));
        mhi = fmaxf(mhi, __shfl_xor_sync(0xffffffffu, mhi, 1));
        mhi = fmaxf(mhi, __shfl_xor_sync(0xffffffffu, mhi, 2));
        if (q == 0){
            mred[wn*64 + r_lo]     = mlo;
            mred[wn*64 + r_lo + 8] = mhi;
        }
        __syncthreads();
        mlo = fmaxf(mred[r_lo],     mred[64 + r_lo]);
        mhi = fmaxf(mred[r_lo + 8], mred[64 + r_lo + 8]);

        // exp, store P (half), row sums
        float slo = 0.f, shi = 0.f;
        #pragma unroll
        for (int nt = 0; nt < 9; nt++){
            const int cc0 = wn*72 + nt*8 + 2*q;
            float p0 = __expf(cs[nt][0] - mlo);
            float p1 = __expf(cs[nt][1] - mlo);
            float p2 = __expf(cs[nt][2] - mhi);
            float p3 = __expf(cs[nt][3] - mhi);
            slo += p0 + p1; shi += p2 + p3;
            *(__half2*)&Ps[(r_lo    ) * PS_STR + cc0] = __floats2half2_rn(p0, p1);
            *(__half2*)&Ps[(r_lo + 8) * PS_STR + cc0] = __floats2half2_rn(p2, p3);
        }
        slo += __shfl_xor_sync(0xffffffffu, slo, 1);
        slo += __shfl_xor_sync(0xffffffffu, slo, 2);
        shi += __shfl_xor_sync(0xffffffffu, shi, 1);
        shi += __shfl_xor_sync(0xffffffffu, shi, 2);
        if (q == 0){
            sred[wn*64 + r_lo]     = slo;
            sred[wn*64 + r_lo + 8] = shi;
        }
    }
    __syncthreads();

    // ---- PV: warps (wm2 rows 16 each, wn2 d-half 32 each) ----
    {
        const int wm2 = warp >> 1, wn2 = warp & 1;
        const int r_lo = wm2*16 + (lane >> 2);
        float co[4][4];
        #pragma unroll
        for (int nt = 0; nt < 4; nt++)
            #pragma unroll
            for (int v = 0; v < 4; v++) co[nt][v] = 0.f;

        #pragma unroll
        for (int ks = 0; ks < 9; ks++){
            const int k0 = ks * 16;
            uint32_t pa[4];
            pa[0] = *(const uint32_t*)&Ps[(r_lo    ) * PS_STR + k0 + 2*q];
            pa[1] = *(const uint32_t*)&Ps[(r_lo + 8) * PS_STR + k0 + 2*q];
            pa[2] = *(const uint32_t*)&Ps[(r_lo    ) * PS_STR + k0 + 8 + 2*q];
            pa[3] = *(const uint32_t*)&Ps[(r_lo + 8) * PS_STR + k0 + 8 + 2*q];
            uint32_t vb[2][4];
            #pragma unroll
            for (int db = 0; db < 2; db++){
                int m_ = lane >> 3;
                int j  = k0 + (lane & 7) + (m_ & 1) * 8;
                int dc = wn2*32 + db*16 + (m_ >> 1) * 8;
                ldm4t(vb[db], uV + SWZ((uint32_t)(j * 128 + dc * 2)));
            }
            #pragma unroll
            for (int nt = 0; nt < 4; nt++){
                const int db = nt >> 1, hi = nt & 1;
                mma16(co[nt], pa, vb[db][hi*2], vb[db][hi*2 + 1]);
            }
        }

        const float rlo = 1.f / (sred[r_lo]     + sred[64 + r_lo]);
        const float rhi = 1.f / (sred[r_lo + 8] + sred[64 + r_lo + 8]);
        #pragma unroll
        for (int nt = 0; nt < 4; nt++){
            const int d0 = wn2*32 + nt*8 + 2*q;
            #pragma unroll
            for (int hf = 0; hf < 2; hf++){
                const int r = r_lo + hf*8;
                const int i = i0 + r;
                if (i >= 4){
                    float sc = hf ? rhi : rlo;
                    __half2 hv = __floats2half2_rn(co[nt][hf*2] * sc, co[nt][hf*2+1] * sc);
                    *(__half2*)(g_att + base + (size_t)i * HD + d0) = hv;
                }
            }
        }
    }
}

// ---------------------------------------------------------------------------
// Global rows (i < 4): dense attention over all 2048 cols, fp32 math.
// ---------------------------------------------------------------------------
__global__ void __launch_bounds__(256)
attn_global()
{
    __shared__ float qs[HD];
    __shared__ float s[SEQ];
    __shared__ float red[256];
    const int tid = threadIdx.x;
    const int r = blockIdx.x, h = blockIdx.y, b = blockIdx.z;
    const size_t base = ((size_t)(b * NH + h)) * SEQ * HD;

    if (tid < HD) qs[tid] = __half2float(g_q[base + (size_t)r * HD + tid]);
    __syncthreads();

    for (int j = tid; j < SEQ; j += 256){
        const __half2* kr = (const __half2*)(g_k + base + (size_t)j * HD);
        float acc = 0.f;
        #pragma unroll
        for (int dd = 0; dd < 32; dd++){
            float2 kv = __half22float2(kr[dd]);
            acc += qs[2*dd] * kv.x + qs[2*dd+1] * kv.y;
        }
        s[j] = acc * ATT_SCALE;
    }
    __syncthreads();

    float lm = NEG;
    for (int j = tid; j < SEQ; j += 256) lm = fmaxf(lm, s[j]);
    red[tid] = lm; __syncthreads();
    for (int off = 128; off; off >>= 1){
        if (tid < off) red[tid] = fmaxf(red[tid], red[tid + off]);
        __syncthreads();
    }
    const float mx = red[0]; __syncthreads();

    float ls = 0.f;
    for (int j = tid; j < SEQ; j += 256){
        float p = __expf(s[j] - mx); s[j] = p; ls += p;
    }
    red[tid] = ls; __syncthreads();
    for (int off = 128; off; off >>= 1){
        if (tid < off) red[tid] += red[tid + off];
        __syncthreads();
    }
    const float ri = 1.f / red[0]; __syncthreads();

    const int d = tid & 63, ch = tid >> 6;
    float acc = 0.f;
    const __half* vb = g_v + base + d;
    for (int j = ch * 512; j < ch * 512 + 512; j++)
        acc += s[j] * __half2float(vb[(size_t)j * HD]);
    red[tid] = acc; __syncthreads();
    if (tid < 64)
        g_att[base + (size_t)r * HD + tid] = __float2half_rn(
            (red[tid] + red[tid + 64] + red[tid + 128] + red[tid + 192]) * ri);
}

// ---------------------------------------------------------------------------
extern "C" void kernel_launch(void* const* d_in, const int* in_sizes, int n_in,
                              void* d_out, int out_size)
{
    const float* x  = (const float*)d_in[0];
    const float* Wq = (const float*)d_in[1];
    const float* bq = (const float*)d_in[2];
    const float* Wk = (const float*)d_in[3];
    const float* bk = (const float*)d_in[4];
    const float* Wv = (const float*)d_in[5];
    const float* bv = (const float*)d_in[6];
    const float* Wo = (const float*)d_in[7];
    const float* bo = (const float*)d_in[8];
    float* out = (float*)d_out;

    const int gsm = NSTG * STG;     // 98304 B
    cudaFuncSetAttribute(gemm_h,    cudaFuncAttributeMaxDynamicSharedMemorySize, gsm);
    cudaFuncSetAttribute(attn_band, cudaFuncAttributeMaxDynamicSharedMemorySize, ATT_SMEM);

    // fp16 conversion prepass
    conv_h<<<(MTOT*HID/8 + 255)/256, 256>>>(x, -1, MTOT*HID/8);
    conv_h<<<(HID*HID/8 + 255)/256, 256>>>(Wq, 0, HID*HID/8);
    conv_h<<<(HID*HID/8 + 255)/256, 256>>>(Wk, 1, HID*HID/8);
    conv_h<<<(HID*HID/8 + 255)/256, 256>>>(Wv, 2, HID*HID/8);
    conv_h<<<(HID*HID/8 + 255)/256, 256>>>(Wo, 3, HID*HID/8);

    // fused QKV projections
    gemm_h<<<dim3(HID/128, MTOT/128, 3), 256, gsm>>>(bq, bk, bv, nullptr, 1);

    // attention
    attn_band<<<dim3(SEQ/64, NH, NB), 256, ATT_SMEM>>>();
    attn_global<<<dim3(4, NH, NB), 256>>>();

    // output projection
    gemm_h<<<dim3(HID/128, MTOT/128, 1), 256, gsm>>>(bo, nullptr, nullptr, out, 0);
}